// round 1
// baseline (speedup 1.0000x reference)
#include <cuda_runtime.h>

// Problem shape (fixed by the reference).
constexpr int B  = 4;
constexpr int L  = 2048;
constexpr int D  = 1024;
constexpr int H  = 16;
constexpr int HD = 64;          // head dim
constexpr int M  = B * L;       // 8192 rows for the projection GEMMs

// Scratch (device globals — no allocation allowed in kernel_launch).
__device__ float g_Q [M * D];
__device__ float g_K [M * D];
__device__ float g_V [M * D];
__device__ float g_AO[M * D];

// ---------------------------------------------------------------------------
// C[M,1024] = A[M,1024] @ W[1024,1024]^T + bias   (torch Linear semantics)
// 64x64 output tile per block, 256 threads, 4x4 microtile, BK=16.
// ---------------------------------------------------------------------------
__global__ __launch_bounds__(256) void gemm_bias_kernel(
    const float* __restrict__ A, const float* __restrict__ W,
    const float* __restrict__ bias, float* __restrict__ C) {
  constexpr int K = 1024;
  constexpr int N = 1024;
  __shared__ float As[64][16];
  __shared__ float Bs[64][16];

  const int tx = threadIdx.x;           // 0..15
  const int ty = threadIdx.y;           // 0..15
  const int t  = ty * 16 + tx;          // 0..255
  const int row0 = blockIdx.y * 64;
  const int col0 = blockIdx.x * 64;

  const int lr = t >> 2;                // 0..63 : tile row this thread loads
  const int lc = (t & 3) * 4;           // 0,4,8,12 : float4 col

  const float* aptr = A + (size_t)(row0 + lr) * K + lc;
  const float* wptr = W + (size_t)(col0 + lr) * K + lc;

  float acc[4][4] = {};

  for (int kt = 0; kt < K; kt += 16) {
    float4 av = *(const float4*)(aptr + kt);
    float4 wv = *(const float4*)(wptr + kt);
    *(float4*)(&As[lr][lc]) = av;
    *(float4*)(&Bs[lr][lc]) = wv;
    __syncthreads();
#pragma unroll
    for (int kk = 0; kk < 16; kk++) {
      float a[4], b[4];
#pragma unroll
      for (int i = 0; i < 4; i++) a[i] = As[ty * 4 + i][kk];
#pragma unroll
      for (int j = 0; j < 4; j++) b[j] = Bs[tx * 4 + j][kk];
#pragma unroll
      for (int i = 0; i < 4; i++)
#pragma unroll
        for (int j = 0; j < 4; j++) acc[i][j] += a[i] * b[j];
    }
    __syncthreads();
  }

  float4 bv = *(const float4*)(bias + col0 + tx * 4);
#pragma unroll
  for (int i = 0; i < 4; i++) {
    float4 r;
    r.x = acc[i][0] + bv.x;
    r.y = acc[i][1] + bv.y;
    r.z = acc[i][2] + bv.z;
    r.w = acc[i][3] + bv.w;
    *(float4*)(&C[(size_t)(row0 + ty * 4 + i) * N + col0 + tx * 4]) = r;
  }
}

// ---------------------------------------------------------------------------
// Flash attention, fp32. One block = one (b,h) pair x 64 query rows.
// One thread owns one query row: q[64] and o[64] live in registers.
// K/V tiles (64x64) staged in shared memory. Online softmax in chunks of 16
// columns so the score vector stays at 16 registers.
// ---------------------------------------------------------------------------
__global__ __launch_bounds__(64) void attention_kernel(
    const float* __restrict__ Qp, const float* __restrict__ Kp,
    const float* __restrict__ Vp, float* __restrict__ Op) {
  __shared__ float Ks[64][64];
  __shared__ float Vs[64][64];

  const int t  = threadIdx.x;           // 0..63 : q row within tile
  const int qt = blockIdx.x;            // q tile index (0..31)
  const int bh = blockIdx.y;            // 0..63
  const int b  = bh >> 4;
  const int h  = bh & 15;
  const int qrow = qt * 64 + t;

  // Load this thread's query row (pre-scaled by 1/sqrt(HD) = 0.125).
  const float* qp = Qp + ((size_t)(b * L + qrow)) * D + h * HD;
  float4 q4[16];
#pragma unroll
  for (int i = 0; i < 16; i++) {
    float4 v = ((const float4*)qp)[i];
    v.x *= 0.125f; v.y *= 0.125f; v.z *= 0.125f; v.w *= 0.125f;
    q4[i] = v;
  }

  float4 o4[16];
#pragma unroll
  for (int i = 0; i < 16; i++) o4[i] = make_float4(0.f, 0.f, 0.f, 0.f);
  float mrun = -1e30f;
  float lrun = 0.f;

  const float* kbase = Kp + ((size_t)(b * L)) * D + h * HD;
  const float* vbase = Vp + ((size_t)(b * L)) * D + h * HD;

  for (int kt = 0; kt < L / 64; kt++) {
    __syncthreads();  // previous tile fully consumed
    const float* kb = kbase + (size_t)kt * 64 * D;
    const float* vb = vbase + (size_t)kt * 64 * D;
    // Cooperative tile load: 64 rows x 16 float4 = 1024 float4, 16 per thread.
#pragma unroll
    for (int i = 0; i < 16; i++) {
      int idx = t + i * 64;
      int r = idx >> 4;
      int c = idx & 15;
      ((float4*)(&Ks[r][0]))[c] = ((const float4*)(kb + (size_t)r * D))[c];
      ((float4*)(&Vs[r][0]))[c] = ((const float4*)(vb + (size_t)r * D))[c];
    }
    __syncthreads();

#pragma unroll
    for (int c = 0; c < 4; c++) {       // 4 chunks of 16 key columns
      float s[16];
#pragma unroll
      for (int j2 = 0; j2 < 16; j2++) {
        const int j = c * 16 + j2;
        const float4* kr = (const float4*)(&Ks[j][0]);
        float s0 = 0.f, s1 = 0.f, s2 = 0.f, s3 = 0.f;
#pragma unroll
        for (int i = 0; i < 16; i++) {
          float4 kv = kr[i];
          s0 += q4[i].x * kv.x;
          s1 += q4[i].y * kv.y;
          s2 += q4[i].z * kv.z;
          s3 += q4[i].w * kv.w;
        }
        s[j2] = (s0 + s1) + (s2 + s3);
      }
      float mx = s[0];
#pragma unroll
      for (int j2 = 1; j2 < 16; j2++) mx = fmaxf(mx, s[j2]);
      const float mnew = fmaxf(mrun, mx);
      const float corr = __expf(mrun - mnew);
      mrun = mnew;
      lrun *= corr;
#pragma unroll
      for (int i = 0; i < 16; i++) {
        o4[i].x *= corr; o4[i].y *= corr;
        o4[i].z *= corr; o4[i].w *= corr;
      }
#pragma unroll
      for (int j2 = 0; j2 < 16; j2++) {
        const int j = c * 16 + j2;
        const float p = __expf(s[j2] - mrun);
        lrun += p;
        const float4* vr = (const float4*)(&Vs[j][0]);
#pragma unroll
        for (int i = 0; i < 16; i++) {
          float4 vv = vr[i];
          o4[i].x += p * vv.x;
          o4[i].y += p * vv.y;
          o4[i].z += p * vv.z;
          o4[i].w += p * vv.w;
        }
      }
    }
  }

  const float inv = 1.f / lrun;
  float* op = Op + ((size_t)(b * L + qrow)) * D + h * HD;
#pragma unroll
  for (int i = 0; i < 16; i++) {
    float4 r = o4[i];
    r.x *= inv; r.y *= inv; r.z *= inv; r.w *= inv;
    ((float4*)op)[i] = r;
  }
}

// ---------------------------------------------------------------------------
extern "C" void kernel_launch(void* const* d_in, const int* in_sizes, int n_in,
                              void* d_out, int out_size) {
  const float* query = (const float*)d_in[0];
  const float* key   = (const float*)d_in[1];
  const float* value = (const float*)d_in[2];
  const float* Wq    = (const float*)d_in[3];
  const float* bq    = (const float*)d_in[4];
  const float* Wk    = (const float*)d_in[5];
  const float* bk    = (const float*)d_in[6];
  const float* Wv    = (const float*)d_in[7];
  const float* bv    = (const float*)d_in[8];
  const float* Wo    = (const float*)d_in[9];
  const float* bo    = (const float*)d_in[10];
  float* out = (float*)d_out;

  float *dQ, *dK, *dV, *dAO;
  cudaGetSymbolAddress((void**)&dQ,  g_Q);
  cudaGetSymbolAddress((void**)&dK,  g_K);
  cudaGetSymbolAddress((void**)&dV,  g_V);
  cudaGetSymbolAddress((void**)&dAO, g_AO);

  dim3 gblk(16, 16);
  dim3 ggrd(1024 / 64, M / 64);   // (N tiles, M tiles)

  gemm_bias_kernel<<<ggrd, gblk>>>(query, Wq, bq, dQ);
  gemm_bias_kernel<<<ggrd, gblk>>>(key,   Wk, bk, dK);
  gemm_bias_kernel<<<ggrd, gblk>>>(value, Wv, bv, dV);

  attention_kernel<<<dim3(L / 64, B * H), 64>>>(dQ, dK, dV, dAO);

  gemm_bias_kernel<<<ggrd, gblk>>>(dAO, Wo, bo, out);
}

// round 3
// speedup vs baseline: 2.2730x; 2.2730x over previous
#include <cuda_runtime.h>
#include <cuda_bf16.h>
#include <cstdint>

// Problem shape (fixed by the reference).
constexpr int B  = 4;
constexpr int L  = 2048;
constexpr int D  = 1024;
constexpr int H  = 16;
constexpr int HD = 64;
constexpr int M  = B * L;       // 8192

// ---------------------------------------------------------------------------
// Scratch (device globals — no allocation allowed).
// ---------------------------------------------------------------------------
__device__ float g_Q [M * D];
__device__ float g_K [M * D];
__device__ float g_V [M * D];
__device__ float g_AO[M * D];
__device__ __nv_bfloat16 g_Ah[M * D];   // activation hi
__device__ __nv_bfloat16 g_Al[M * D];   // activation lo
__device__ __nv_bfloat16 g_Wh[D * D];   // weight hi
__device__ __nv_bfloat16 g_Wl[D * D];   // weight lo

// ---------------------------------------------------------------------------
// Warp-level bf16 MMA (baseline PTX, runs on tensor pipe as HMMA).
// D(f32) += A(bf16,row) * B(bf16,col)
// ---------------------------------------------------------------------------
__device__ __forceinline__ void mma16816(float& d0, float& d1, float& d2,
                                         float& d3, uint32_t a0, uint32_t a1,
                                         uint32_t a2, uint32_t a3, uint32_t b0,
                                         uint32_t b1) {
  asm volatile(
      "mma.sync.aligned.m16n8k16.row.col.f32.bf16.bf16.f32 "
      "{%0,%1,%2,%3}, {%4,%5,%6,%7}, {%8,%9}, {%0,%1,%2,%3};"
      : "+f"(d0), "+f"(d1), "+f"(d2), "+f"(d3)
      : "r"(a0), "r"(a1), "r"(a2), "r"(a3), "r"(b0), "r"(b1));
}

// ---------------------------------------------------------------------------
// fp32 -> bf16 hi/lo split (x = hi + lo + O(2^-18 x))
// ---------------------------------------------------------------------------
__global__ __launch_bounds__(256) void split_bf16_kernel(
    const float* __restrict__ x, __nv_bfloat16* __restrict__ hi,
    __nv_bfloat16* __restrict__ lo, int n) {
  int i = (blockIdx.x * 256 + threadIdx.x) * 4;
  if (i >= n) return;
  float4 v = *(const float4*)(x + i);
  __nv_bfloat16 h[4], l[4];
  float vv[4] = {v.x, v.y, v.z, v.w};
#pragma unroll
  for (int j = 0; j < 4; j++) {
    h[j] = __float2bfloat16(vv[j]);
    l[j] = __float2bfloat16(vv[j] - __bfloat162float(h[j]));
  }
  *(uint2*)(hi + i) = *(uint2*)h;
  *(uint2*)(lo + i) = *(uint2*)l;
}

// ---------------------------------------------------------------------------
// Warp-MMA GEMM: C[M,1024] = A[M,1024] @ W[1024,1024]^T + bias  (bf16x3)
// CTA tile 128x128, 8 warps (2x4) of 64x32, BK=32, double-buffered smem.
// K loop runs 3 passes: Ah*Wh, Ah*Wl, Al*Wh accumulating in registers.
// Smem rows padded to 40 halves (80B) -> conflict-free fragment loads.
// ---------------------------------------------------------------------------
constexpr int KDIM = 1024;
constexpr int BM = 128, BN = 128, BKC = 32;
constexpr int NCH = 3 * (KDIM / BKC);   // 96 chunks

__global__ __launch_bounds__(256) void gemm_mma_kernel(
    const __nv_bfloat16* __restrict__ Ah, const __nv_bfloat16* __restrict__ Al,
    const __nv_bfloat16* __restrict__ Wh, const __nv_bfloat16* __restrict__ Wl,
    const float* __restrict__ bias, float* __restrict__ C) {
  __shared__ __nv_bfloat16 As[2][BM][40];
  __shared__ __nv_bfloat16 Bs[2][BN][40];

  const int tid  = threadIdx.x;
  const int wid  = tid >> 5;
  const int lane = tid & 31;
  const int quad = lane >> 2;       // groupID 0..7
  const int pair = lane & 3;        // tid-in-group 0..3
  const int m0 = blockIdx.y * BM;
  const int n0 = blockIdx.x * BN;
  const int mbase = (wid >> 2) * 64;    // warp row 0/64
  const int nbase = (wid & 3) * 32;     // warp col 0/32/64/96

  const __nv_bfloat16* Aops[3] = {Ah, Ah, Al};
  const __nv_bfloat16* Bops[3] = {Wh, Wl, Wh};

  float acc[4][4][4];
#pragma unroll
  for (int i = 0; i < 4; i++)
#pragma unroll
    for (int j = 0; j < 4; j++)
#pragma unroll
      for (int k = 0; k < 4; k++) acc[i][j][k] = 0.f;

  // Load-thread mapping: unit u = tid + 256*i covers 128 rows x 4 uint4 cols.
  const int lr0 = tid >> 2;         // row for i=0 (0..63)
  const int lc  = (tid & 3) * 8;    // half-col 0/8/16/24

  // Prologue: load chunk 0 into stage 0.
  {
    const __nv_bfloat16* ag = Aops[0] + (size_t)m0 * KDIM;
    const __nv_bfloat16* bg = Bops[0] + (size_t)n0 * KDIM;
#pragma unroll
    for (int i = 0; i < 2; i++) {
      int r = lr0 + i * 64;
      *(uint4*)(&As[0][r][lc]) = *(const uint4*)(ag + (size_t)r * KDIM + lc);
      *(uint4*)(&Bs[0][r][lc]) = *(const uint4*)(bg + (size_t)r * KDIM + lc);
    }
  }
  __syncthreads();

  for (int ch = 0; ch < NCH; ch++) {
    const int st = ch & 1;
    // Prefetch next chunk into registers.
    uint4 pa[2], pb[2];
    const bool havenext = (ch + 1 < NCH);
    if (havenext) {
      const int p  = (ch + 1) >> 5;
      const int kc = ((ch + 1) & 31) * BKC;
      const __nv_bfloat16* ag = Aops[p] + (size_t)m0 * KDIM + kc;
      const __nv_bfloat16* bg = Bops[p] + (size_t)n0 * KDIM + kc;
#pragma unroll
      for (int i = 0; i < 2; i++) {
        int r = lr0 + i * 64;
        pa[i] = *(const uint4*)(ag + (size_t)r * KDIM + lc);
        pb[i] = *(const uint4*)(bg + (size_t)r * KDIM + lc);
      }
    }
    // Compute on current stage: 2 k16 steps.
#pragma unroll
    for (int ks = 0; ks < 2; ks++) {
      const int col = ks * 16 + pair * 2;
      uint32_t a[4][4], b[4][2];
#pragma unroll
      for (int mt = 0; mt < 4; mt++) {
        int row = mbase + mt * 16 + quad;
        a[mt][0] = *(const uint32_t*)(&As[st][row][col]);
        a[mt][1] = *(const uint32_t*)(&As[st][row + 8][col]);
        a[mt][2] = *(const uint32_t*)(&As[st][row][col + 8]);
        a[mt][3] = *(const uint32_t*)(&As[st][row + 8][col + 8]);
      }
#pragma unroll
      for (int nt = 0; nt < 4; nt++) {
        int rw = nbase + nt * 8 + quad;
        b[nt][0] = *(const uint32_t*)(&Bs[st][rw][col]);
        b[nt][1] = *(const uint32_t*)(&Bs[st][rw][col + 8]);
      }
#pragma unroll
      for (int mt = 0; mt < 4; mt++)
#pragma unroll
        for (int nt = 0; nt < 4; nt++)
          mma16816(acc[mt][nt][0], acc[mt][nt][1], acc[mt][nt][2],
                   acc[mt][nt][3], a[mt][0], a[mt][1], a[mt][2], a[mt][3],
                   b[nt][0], b[nt][1]);
    }
    if (havenext) {
      const int nst = st ^ 1;
#pragma unroll
      for (int i = 0; i < 2; i++) {
        int r = lr0 + i * 64;
        *(uint4*)(&As[nst][r][lc]) = pa[i];
        *(uint4*)(&Bs[nst][r][lc]) = pb[i];
      }
    }
    __syncthreads();
  }

  // Epilogue: acc[mt][nt] -> C rows (mbase+mt*16+quad, +8), cols nt*8+pair*2.
#pragma unroll
  for (int mt = 0; mt < 4; mt++) {
    int row = m0 + mbase + mt * 16 + quad;
#pragma unroll
    for (int nt = 0; nt < 4; nt++) {
      int col = n0 + nbase + nt * 8 + pair * 2;
      float2 bv = *(const float2*)(bias + col);
      float2 r0, r1;
      r0.x = acc[mt][nt][0] + bv.x;
      r0.y = acc[mt][nt][1] + bv.y;
      r1.x = acc[mt][nt][2] + bv.x;
      r1.y = acc[mt][nt][3] + bv.y;
      *(float2*)(C + (size_t)row * KDIM + col) = r0;
      *(float2*)(C + (size_t)(row + 8) * KDIM + col) = r1;
    }
  }
}

// ---------------------------------------------------------------------------
// Flash attention, fp32 (unchanged from R1 — isolates the GEMM change).
// ---------------------------------------------------------------------------
__global__ __launch_bounds__(64) void attention_kernel(
    const float* __restrict__ Qp, const float* __restrict__ Kp,
    const float* __restrict__ Vp, float* __restrict__ Op) {
  __shared__ float Ks[64][64];
  __shared__ float Vs[64][64];

  const int t  = threadIdx.x;
  const int qt = blockIdx.x;
  const int bh = blockIdx.y;
  const int b  = bh >> 4;
  const int h  = bh & 15;
  const int qrow = qt * 64 + t;

  const float* qp = Qp + ((size_t)(b * L + qrow)) * D + h * HD;
  float4 q4[16];
#pragma unroll
  for (int i = 0; i < 16; i++) {
    float4 v = ((const float4*)qp)[i];
    v.x *= 0.125f; v.y *= 0.125f; v.z *= 0.125f; v.w *= 0.125f;
    q4[i] = v;
  }

  float4 o4[16];
#pragma unroll
  for (int i = 0; i < 16; i++) o4[i] = make_float4(0.f, 0.f, 0.f, 0.f);
  float mrun = -1e30f;
  float lrun = 0.f;

  const float* kbase = Kp + ((size_t)(b * L)) * D + h * HD;
  const float* vbase = Vp + ((size_t)(b * L)) * D + h * HD;

  for (int kt = 0; kt < L / 64; kt++) {
    __syncthreads();
    const float* kb = kbase + (size_t)kt * 64 * D;
    const float* vb = vbase + (size_t)kt * 64 * D;
#pragma unroll
    for (int i = 0; i < 16; i++) {
      int idx = t + i * 64;
      int r = idx >> 4;
      int c = idx & 15;
      ((float4*)(&Ks[r][0]))[c] = ((const float4*)(kb + (size_t)r * D))[c];
      ((float4*)(&Vs[r][0]))[c] = ((const float4*)(vb + (size_t)r * D))[c];
    }
    __syncthreads();

#pragma unroll
    for (int c = 0; c < 4; c++) {
      float s[16];
#pragma unroll
      for (int j2 = 0; j2 < 16; j2++) {
        const int j = c * 16 + j2;
        const float4* kr = (const float4*)(&Ks[j][0]);
        float s0 = 0.f, s1 = 0.f, s2 = 0.f, s3 = 0.f;
#pragma unroll
        for (int i = 0; i < 16; i++) {
          float4 kv = kr[i];
          s0 += q4[i].x * kv.x;
          s1 += q4[i].y * kv.y;
          s2 += q4[i].z * kv.z;
          s3 += q4[i].w * kv.w;
        }
        s[j2] = (s0 + s1) + (s2 + s3);
      }
      float mx = s[0];
#pragma unroll
      for (int j2 = 1; j2 < 16; j2++) mx = fmaxf(mx, s[j2]);
      const float mnew = fmaxf(mrun, mx);
      const float corr = __expf(mrun - mnew);
      mrun = mnew;
      lrun *= corr;
#pragma unroll
      for (int i = 0; i < 16; i++) {
        o4[i].x *= corr; o4[i].y *= corr;
        o4[i].z *= corr; o4[i].w *= corr;
      }
#pragma unroll
      for (int j2 = 0; j2 < 16; j2++) {
        const int j = c * 16 + j2;
        const float p = __expf(s[j2] - mrun);
        lrun += p;
        const float4* vr = (const float4*)(&Vs[j][0]);
#pragma unroll
        for (int i = 0; i < 16; i++) {
          float4 vv = vr[i];
          o4[i].x += p * vv.x;
          o4[i].y += p * vv.y;
          o4[i].z += p * vv.z;
          o4[i].w += p * vv.w;
        }
      }
    }
  }

  const float inv = 1.f / lrun;
  float* op = Op + ((size_t)(b * L + qrow)) * D + h * HD;
#pragma unroll
  for (int i = 0; i < 16; i++) {
    float4 r = o4[i];
    r.x *= inv; r.y *= inv; r.z *= inv; r.w *= inv;
    ((float4*)op)[i] = r;
  }
}

// ---------------------------------------------------------------------------
extern "C" void kernel_launch(void* const* d_in, const int* in_sizes, int n_in,
                              void* d_out, int out_size) {
  const float* query = (const float*)d_in[0];
  const float* key   = (const float*)d_in[1];
  const float* value = (const float*)d_in[2];
  const float* Wq    = (const float*)d_in[3];
  const float* bq    = (const float*)d_in[4];
  const float* Wk    = (const float*)d_in[5];
  const float* bk    = (const float*)d_in[6];
  const float* Wv    = (const float*)d_in[7];
  const float* bv    = (const float*)d_in[8];
  const float* Wo    = (const float*)d_in[9];
  const float* bo    = (const float*)d_in[10];
  float* out = (float*)d_out;

  float *dQ, *dK, *dV, *dAO;
  __nv_bfloat16 *dAh, *dAl, *dWh, *dWl;
  cudaGetSymbolAddress((void**)&dQ,  g_Q);
  cudaGetSymbolAddress((void**)&dK,  g_K);
  cudaGetSymbolAddress((void**)&dV,  g_V);
  cudaGetSymbolAddress((void**)&dAO, g_AO);
  cudaGetSymbolAddress((void**)&dAh, g_Ah);
  cudaGetSymbolAddress((void**)&dAl, g_Al);
  cudaGetSymbolAddress((void**)&dWh, g_Wh);
  cudaGetSymbolAddress((void**)&dWl, g_Wl);

  const int nAct = M * D;            // 8388608
  const int nW   = D * D;            // 1048576
  const int grAct = nAct / 4 / 256;
  const int grW   = nW / 4 / 256;
  dim3 ggrid(D / BN, M / BM);        // (8, 64)

  // Q projection
  split_bf16_kernel<<<grW,   256>>>(Wq,    dWh, dWl, nW);
  split_bf16_kernel<<<grAct, 256>>>(query, dAh, dAl, nAct);
  gemm_mma_kernel<<<ggrid, 256>>>(dAh, dAl, dWh, dWl, bq, dQ);
  // K projection
  split_bf16_kernel<<<grW,   256>>>(Wk,  dWh, dWl, nW);
  split_bf16_kernel<<<grAct, 256>>>(key, dAh, dAl, nAct);
  gemm_mma_kernel<<<ggrid, 256>>>(dAh, dAl, dWh, dWl, bk, dK);
  // V projection
  split_bf16_kernel<<<grW,   256>>>(Wv,    dWh, dWl, nW);
  split_bf16_kernel<<<grAct, 256>>>(value, dAh, dAl, nAct);
  gemm_mma_kernel<<<ggrid, 256>>>(dAh, dAl, dWh, dWl, bv, dV);

  // Attention
  attention_kernel<<<dim3(L / 64, B * H), 64>>>(dQ, dK, dV, dAO);

  // Output projection
  split_bf16_kernel<<<grW,   256>>>(Wo,  dWh, dWl, nW);
  split_bf16_kernel<<<grAct, 256>>>(dAO, dAh, dAl, nAct);
  gemm_mma_kernel<<<ggrid, 256>>>(dAh, dAl, dWh, dWl, bo, out);
}

// round 4
// speedup vs baseline: 8.3521x; 3.6745x over previous
#include <cuda_runtime.h>
#include <cuda_bf16.h>
#include <cstdint>

// Problem shape (fixed by the reference).
constexpr int B  = 4;
constexpr int L  = 2048;
constexpr int D  = 1024;
constexpr int H  = 16;
constexpr int HD = 64;
constexpr int M  = B * L;       // 8192

// ---------------------------------------------------------------------------
// Scratch (device globals — no allocation allowed).
// ---------------------------------------------------------------------------
__device__ __nv_bfloat16 g_Qh[M * D];
__device__ __nv_bfloat16 g_Ql[M * D];
__device__ __nv_bfloat16 g_Kh[M * D];
__device__ __nv_bfloat16 g_Kl[M * D];
__device__ __nv_bfloat16 g_Vh[M * D];
__device__ __nv_bfloat16 g_Vl[M * D];
__device__ __nv_bfloat16 g_Ah[M * D];   // activation hi (also attention out hi)
__device__ __nv_bfloat16 g_Al[M * D];   // activation lo (also attention out lo)
__device__ __nv_bfloat16 g_Wh[D * D];   // weight hi
__device__ __nv_bfloat16 g_Wl[D * D];   // weight lo

// ---------------------------------------------------------------------------
// Helpers
// ---------------------------------------------------------------------------
__device__ __forceinline__ void mma16816(float& d0, float& d1, float& d2,
                                         float& d3, uint32_t a0, uint32_t a1,
                                         uint32_t a2, uint32_t a3, uint32_t b0,
                                         uint32_t b1) {
  asm volatile(
      "mma.sync.aligned.m16n8k16.row.col.f32.bf16.bf16.f32 "
      "{%0,%1,%2,%3}, {%4,%5,%6,%7}, {%8,%9}, {%0,%1,%2,%3};"
      : "+f"(d0), "+f"(d1), "+f"(d2), "+f"(d3)
      : "r"(a0), "r"(a1), "r"(a2), "r"(a3), "r"(b0), "r"(b1));
}

__device__ __forceinline__ uint32_t smem_u32(const void* p) {
  uint32_t a;
  asm("{ .reg .u64 t; cvta.to.shared.u64 t, %1; cvt.u32.u64 %0, t; }"
      : "=r"(a) : "l"(p));
  return a;
}

__device__ __forceinline__ float ex2f(float x) {
  float r;
  asm("ex2.approx.f32 %0, %1;" : "=f"(r) : "f"(x));
  return r;
}

// Pack two fp32 into bf16x2 hi fragment + bf16x2 lo (residual) fragment.
__device__ __forceinline__ void pack_hilo(float x, float y, uint32_t& hi,
                                          uint32_t& lo) {
  __nv_bfloat162 h2 = __float22bfloat162_rn(make_float2(x, y));  // .x -> low
  float hx = __low2float(h2), hy = __high2float(h2);
  __nv_bfloat162 l2 = __float22bfloat162_rn(make_float2(x - hx, y - hy));
  hi = *(uint32_t*)&h2;
  lo = *(uint32_t*)&l2;
}

#define CP_ASYNC16(sa, ga) \
  asm volatile("cp.async.cg.shared.global [%0], [%1], 16;" :: "r"(sa), "l"(ga))
#define CP_COMMIT() asm volatile("cp.async.commit_group;")

// ---------------------------------------------------------------------------
// fp32 -> bf16 hi/lo split (x = hi + lo + O(2^-18 x))
// ---------------------------------------------------------------------------
__global__ __launch_bounds__(256) void split_bf16_kernel(
    const float* __restrict__ x, __nv_bfloat16* __restrict__ hi,
    __nv_bfloat16* __restrict__ lo, int n) {
  int i = (blockIdx.x * 256 + threadIdx.x) * 4;
  if (i >= n) return;
  float4 v = *(const float4*)(x + i);
  __nv_bfloat16 h[4], l[4];
  float vv[4] = {v.x, v.y, v.z, v.w};
#pragma unroll
  for (int j = 0; j < 4; j++) {
    h[j] = __float2bfloat16(vv[j]);
    l[j] = __float2bfloat16(vv[j] - __bfloat162float(h[j]));
  }
  *(uint2*)(hi + i) = *(uint2*)h;
  *(uint2*)(lo + i) = *(uint2*)l;
}

// ---------------------------------------------------------------------------
// Warp-MMA GEMM: C[M,1024] = A[M,1024] @ W[1024,1024]^T + bias  (bf16x3)
// SPLIT_OUT=true: write bf16 hi/lo (for Q/K/V).  false: fp32 C (final out).
// ---------------------------------------------------------------------------
constexpr int KDIM = 1024;
constexpr int BM = 128, BN = 128;
constexpr int NCH = 96;   // 3 passes x 32 chunks of BK=32

template <bool SPLIT_OUT>
__global__ __launch_bounds__(256) void gemm_mma_kernel(
    const __nv_bfloat16* __restrict__ Ah, const __nv_bfloat16* __restrict__ Al,
    const __nv_bfloat16* __restrict__ Wh, const __nv_bfloat16* __restrict__ Wl,
    const float* __restrict__ bias, float* __restrict__ C,
    __nv_bfloat16* __restrict__ Ch, __nv_bfloat16* __restrict__ Cl) {
  __shared__ __nv_bfloat16 As[2][BM][40];
  __shared__ __nv_bfloat16 Bs[2][BN][40];

  const int tid  = threadIdx.x;
  const int wid  = tid >> 5;
  const int lane = tid & 31;
  const int quad = lane >> 2;
  const int pair = lane & 3;
  const int m0 = blockIdx.y * BM;
  const int n0 = blockIdx.x * BN;
  const int mbase = (wid >> 2) * 64;
  const int nbase = (wid & 3) * 32;

  const __nv_bfloat16* Aops[3] = {Ah, Ah, Al};
  const __nv_bfloat16* Bops[3] = {Wh, Wl, Wh};

  float acc[4][4][4];
#pragma unroll
  for (int i = 0; i < 4; i++)
#pragma unroll
    for (int j = 0; j < 4; j++)
#pragma unroll
      for (int k = 0; k < 4; k++) acc[i][j][k] = 0.f;

  const int lr0 = tid >> 2;
  const int lc  = (tid & 3) * 8;

  {
    const __nv_bfloat16* ag = Aops[0] + (size_t)m0 * KDIM;
    const __nv_bfloat16* bg = Bops[0] + (size_t)n0 * KDIM;
#pragma unroll
    for (int i = 0; i < 2; i++) {
      int r = lr0 + i * 64;
      *(uint4*)(&As[0][r][lc]) = *(const uint4*)(ag + (size_t)r * KDIM + lc);
      *(uint4*)(&Bs[0][r][lc]) = *(const uint4*)(bg + (size_t)r * KDIM + lc);
    }
  }
  __syncthreads();

  for (int ch = 0; ch < NCH; ch++) {
    const int st = ch & 1;
    uint4 pa[2], pb[2];
    const bool havenext = (ch + 1 < NCH);
    if (havenext) {
      const int p  = (ch + 1) >> 5;
      const int kc = ((ch + 1) & 31) * 32;
      const __nv_bfloat16* ag = Aops[p] + (size_t)m0 * KDIM + kc;
      const __nv_bfloat16* bg = Bops[p] + (size_t)n0 * KDIM + kc;
#pragma unroll
      for (int i = 0; i < 2; i++) {
        int r = lr0 + i * 64;
        pa[i] = *(const uint4*)(ag + (size_t)r * KDIM + lc);
        pb[i] = *(const uint4*)(bg + (size_t)r * KDIM + lc);
      }
    }
#pragma unroll
    for (int ks = 0; ks < 2; ks++) {
      const int col = ks * 16 + pair * 2;
      uint32_t a[4][4], b[4][2];
#pragma unroll
      for (int mt = 0; mt < 4; mt++) {
        int row = mbase + mt * 16 + quad;
        a[mt][0] = *(const uint32_t*)(&As[st][row][col]);
        a[mt][1] = *(const uint32_t*)(&As[st][row + 8][col]);
        a[mt][2] = *(const uint32_t*)(&As[st][row][col + 8]);
        a[mt][3] = *(const uint32_t*)(&As[st][row + 8][col + 8]);
      }
#pragma unroll
      for (int nt = 0; nt < 4; nt++) {
        int rw = nbase + nt * 8 + quad;
        b[nt][0] = *(const uint32_t*)(&Bs[st][rw][col]);
        b[nt][1] = *(const uint32_t*)(&Bs[st][rw][col + 8]);
      }
#pragma unroll
      for (int mt = 0; mt < 4; mt++)
#pragma unroll
        for (int nt = 0; nt < 4; nt++)
          mma16816(acc[mt][nt][0], acc[mt][nt][1], acc[mt][nt][2],
                   acc[mt][nt][3], a[mt][0], a[mt][1], a[mt][2], a[mt][3],
                   b[nt][0], b[nt][1]);
    }
    if (havenext) {
      const int nst = st ^ 1;
#pragma unroll
      for (int i = 0; i < 2; i++) {
        int r = lr0 + i * 64;
        *(uint4*)(&As[nst][r][lc]) = pa[i];
        *(uint4*)(&Bs[nst][r][lc]) = pb[i];
      }
    }
    __syncthreads();
  }

#pragma unroll
  for (int mt = 0; mt < 4; mt++) {
    int row = m0 + mbase + mt * 16 + quad;
#pragma unroll
    for (int nt = 0; nt < 4; nt++) {
      int col = n0 + nbase + nt * 8 + pair * 2;
      float2 bv = *(const float2*)(bias + col);
      float v00 = acc[mt][nt][0] + bv.x;
      float v01 = acc[mt][nt][1] + bv.y;
      float v10 = acc[mt][nt][2] + bv.x;
      float v11 = acc[mt][nt][3] + bv.y;
      if (SPLIT_OUT) {
        uint32_t h0, l0, h1, l1;
        pack_hilo(v00, v01, h0, l0);
        pack_hilo(v10, v11, h1, l1);
        *(uint32_t*)(Ch + (size_t)row * KDIM + col) = h0;
        *(uint32_t*)(Cl + (size_t)row * KDIM + col) = l0;
        *(uint32_t*)(Ch + (size_t)(row + 8) * KDIM + col) = h1;
        *(uint32_t*)(Cl + (size_t)(row + 8) * KDIM + col) = l1;
      } else {
        *(float2*)(C + (size_t)row * KDIM + col) = make_float2(v00, v01);
        *(float2*)(C + (size_t)(row + 8) * KDIM + col) = make_float2(v10, v11);
      }
    }
  }
}

// ---------------------------------------------------------------------------
// Flash attention with warp-MMA, bf16 hi/lo x3 for both QK^T and PV.
// CTA: one (b,h), 128 q rows, 8 warps x 16 rows. K-tiles of 64 tokens,
// cp.async double-buffered. Output written as bf16 hi/lo into Oh/Ol.
// ---------------------------------------------------------------------------
constexpr int NKT = L / 64;                 // 32 k-tiles
constexpr int ROWH = 72;                    // padded row, halves (144 B)
constexpr int MAT_B = 64 * ROWH * 2;        // 9216 B per matrix tile
constexpr int STAGE_B = 4 * MAT_B;          // Kh,Kl,Vh,Vl
constexpr int AT_SMEM = 2 * STAGE_B;        // 73728 B

__global__ __launch_bounds__(256) void attention_mma_kernel(
    const __nv_bfloat16* __restrict__ Qh, const __nv_bfloat16* __restrict__ Ql,
    const __nv_bfloat16* __restrict__ Kh, const __nv_bfloat16* __restrict__ Kl,
    const __nv_bfloat16* __restrict__ Vh, const __nv_bfloat16* __restrict__ Vl,
    __nv_bfloat16* __restrict__ Oh, __nv_bfloat16* __restrict__ Ol) {
  extern __shared__ char smc[];
  const uint32_t smb = smem_u32(smc);

  const int tid  = threadIdx.x;
  const int wid  = tid >> 5;
  const int lane = tid & 31;
  const int quad = lane >> 2;
  const int pair = lane & 3;
  const int qt = blockIdx.x;          // 0..15
  const int bh = blockIdx.y;          // 0..63
  const int b  = bh >> 4;
  const int h  = bh & 15;
  const int hoff = h * HD;

  // ---- Q fragments (persistent) ----
  const int qrow = qt * 128 + wid * 16 + quad;
  const __nv_bfloat16* qhp = Qh + (size_t)(b * L + qrow) * D + hoff;
  const __nv_bfloat16* qlp = Ql + (size_t)(b * L + qrow) * D + hoff;
  uint32_t qfh[4][4], qfl[4][4];
#pragma unroll
  for (int ks = 0; ks < 4; ks++) {
    const int c0 = ks * 16 + pair * 2;
    qfh[ks][0] = *(const uint32_t*)(qhp + c0);
    qfh[ks][1] = *(const uint32_t*)(qhp + (size_t)8 * D + c0);
    qfh[ks][2] = *(const uint32_t*)(qhp + c0 + 8);
    qfh[ks][3] = *(const uint32_t*)(qhp + (size_t)8 * D + c0 + 8);
    qfl[ks][0] = *(const uint32_t*)(qlp + c0);
    qfl[ks][1] = *(const uint32_t*)(qlp + (size_t)8 * D + c0);
    qfl[ks][2] = *(const uint32_t*)(qlp + c0 + 8);
    qfl[ks][3] = *(const uint32_t*)(qlp + (size_t)8 * D + c0 + 8);
  }

  float o[8][4];
#pragma unroll
  for (int nt = 0; nt < 8; nt++)
#pragma unroll
    for (int j = 0; j < 4; j++) o[nt][j] = 0.f;
  float mrow[2] = {-1e30f, -1e30f};
  float lrow[2] = {0.f, 0.f};

  const __nv_bfloat16* mats[4] = {Kh, Kl, Vh, Vl};
  // cp.async tile issue: per matrix, thread copies 2 x 16B units.
  const int crow0 = tid >> 3;         // 0..31
  const int ccol  = (tid & 7) * 8;    // halves
  auto issue_tile = [&](int kt, int stg) {
#pragma unroll
    for (int mi = 0; mi < 4; mi++) {
      const __nv_bfloat16* g0 =
          mats[mi] + (size_t)(b * L + kt * 64 + crow0) * D + hoff + ccol;
      uint32_t s0 = smb + stg * STAGE_B + mi * MAT_B + crow0 * 144 + ccol * 2;
      CP_ASYNC16(s0, g0);
      CP_ASYNC16(s0 + 32 * 144, g0 + (size_t)32 * D);
    }
    CP_COMMIT();
  };

  issue_tile(0, 0);
  const float SC = 0.125f * 1.44269504f;  // 1/sqrt(HD) * log2(e)

  for (int kt = 0; kt < NKT; kt++) {
    const int st = kt & 1;
    if (kt + 1 < NKT) {
      issue_tile(kt + 1, st ^ 1);
      asm volatile("cp.async.wait_group 1;");
    } else {
      asm volatile("cp.async.wait_group 0;");
    }
    __syncthreads();

    const uint32_t kh_b = smb + st * STAGE_B;
    const uint32_t kl_b = kh_b + MAT_B;
    const uint32_t vh_b = kh_b + 2 * MAT_B;
    const uint32_t vl_b = kh_b + 3 * MAT_B;

    // ---- S = Q K^T (3 passes) ----
    float s[8][4];
#pragma unroll
    for (int nt = 0; nt < 8; nt++)
#pragma unroll
      for (int j = 0; j < 4; j++) s[nt][j] = 0.f;

#pragma unroll
    for (int ks = 0; ks < 4; ks++) {
      const int col = ks * 32 + pair * 4;     // byte offset in row
#pragma unroll
      for (int nt = 0; nt < 8; nt++) {
        const uint32_t ro = (uint32_t)((nt * 8 + quad) * 144 + col);
        uint32_t bh0, bh1, bl0, bl1;
        asm("ld.shared.b32 %0, [%1];" : "=r"(bh0) : "r"(kh_b + ro));
        asm("ld.shared.b32 %0, [%1];" : "=r"(bh1) : "r"(kh_b + ro + 16));
        asm("ld.shared.b32 %0, [%1];" : "=r"(bl0) : "r"(kl_b + ro));
        asm("ld.shared.b32 %0, [%1];" : "=r"(bl1) : "r"(kl_b + ro + 16));
        mma16816(s[nt][0], s[nt][1], s[nt][2], s[nt][3],
                 qfh[ks][0], qfh[ks][1], qfh[ks][2], qfh[ks][3], bh0, bh1);
        mma16816(s[nt][0], s[nt][1], s[nt][2], s[nt][3],
                 qfl[ks][0], qfl[ks][1], qfl[ks][2], qfl[ks][3], bh0, bh1);
        mma16816(s[nt][0], s[nt][1], s[nt][2], s[nt][3],
                 qfh[ks][0], qfh[ks][1], qfh[ks][2], qfh[ks][3], bl0, bl1);
      }
    }

    // ---- online softmax (exp2 domain, scale folded) ----
    float rx0 = -1e30f, rx1 = -1e30f;
#pragma unroll
    for (int nt = 0; nt < 8; nt++) {
      s[nt][0] *= SC; s[nt][1] *= SC; s[nt][2] *= SC; s[nt][3] *= SC;
      rx0 = fmaxf(rx0, fmaxf(s[nt][0], s[nt][1]));
      rx1 = fmaxf(rx1, fmaxf(s[nt][2], s[nt][3]));
    }
    rx0 = fmaxf(rx0, __shfl_xor_sync(0xffffffff, rx0, 1));
    rx0 = fmaxf(rx0, __shfl_xor_sync(0xffffffff, rx0, 2));
    rx1 = fmaxf(rx1, __shfl_xor_sync(0xffffffff, rx1, 1));
    rx1 = fmaxf(rx1, __shfl_xor_sync(0xffffffff, rx1, 2));
    const float mn0 = fmaxf(mrow[0], rx0);
    const float mn1 = fmaxf(mrow[1], rx1);
    const float c0 = ex2f(mrow[0] - mn0);
    const float c1 = ex2f(mrow[1] - mn1);
    mrow[0] = mn0; mrow[1] = mn1;
    float ls0 = 0.f, ls1 = 0.f;
#pragma unroll
    for (int nt = 0; nt < 8; nt++) {
      o[nt][0] *= c0; o[nt][1] *= c0; o[nt][2] *= c1; o[nt][3] *= c1;
      s[nt][0] = ex2f(s[nt][0] - mn0);
      s[nt][1] = ex2f(s[nt][1] - mn0);
      s[nt][2] = ex2f(s[nt][2] - mn1);
      s[nt][3] = ex2f(s[nt][3] - mn1);
      ls0 += s[nt][0] + s[nt][1];
      ls1 += s[nt][2] + s[nt][3];
    }
    lrow[0] = lrow[0] * c0 + ls0;
    lrow[1] = lrow[1] * c1 + ls1;

    // ---- O += P V (3 passes, P frags straight from registers) ----
#pragma unroll
    for (int ks = 0; ks < 4; ks++) {
      uint32_t ah[4], al[4];
      pack_hilo(s[2 * ks][0],     s[2 * ks][1],     ah[0], al[0]);
      pack_hilo(s[2 * ks][2],     s[2 * ks][3],     ah[1], al[1]);
      pack_hilo(s[2 * ks + 1][0], s[2 * ks + 1][1], ah[2], al[2]);
      pack_hilo(s[2 * ks + 1][2], s[2 * ks + 1][3], ah[3], al[3]);
      const uint32_t vrow = (uint32_t)((ks * 16 + (lane & 15)) * 144);
#pragma unroll
      for (int nt = 0; nt < 8; nt++) {
        uint32_t vh0, vh1, vl0, vl1;
        asm volatile(
            "ldmatrix.sync.aligned.m8n8.x2.trans.shared.b16 {%0,%1}, [%2];"
            : "=r"(vh0), "=r"(vh1) : "r"(vh_b + vrow + nt * 16));
        asm volatile(
            "ldmatrix.sync.aligned.m8n8.x2.trans.shared.b16 {%0,%1}, [%2];"
            : "=r"(vl0), "=r"(vl1) : "r"(vl_b + vrow + nt * 16));
        mma16816(o[nt][0], o[nt][1], o[nt][2], o[nt][3],
                 ah[0], ah[1], ah[2], ah[3], vh0, vh1);
        mma16816(o[nt][0], o[nt][1], o[nt][2], o[nt][3],
                 al[0], al[1], al[2], al[3], vh0, vh1);
        mma16816(o[nt][0], o[nt][1], o[nt][2], o[nt][3],
                 ah[0], ah[1], ah[2], ah[3], vl0, vl1);
      }
    }
    __syncthreads();
  }

  // ---- finalize: normalize, split hi/lo, store ----
  float lf0 = lrow[0];
  lf0 += __shfl_xor_sync(0xffffffff, lf0, 1);
  lf0 += __shfl_xor_sync(0xffffffff, lf0, 2);
  float lf1 = lrow[1];
  lf1 += __shfl_xor_sync(0xffffffff, lf1, 1);
  lf1 += __shfl_xor_sync(0xffffffff, lf1, 2);
  const float i0 = 1.f / lf0;
  const float i1 = 1.f / lf1;

  const size_t r0 = (size_t)(b * L + qrow) * D + hoff;
  const size_t r1 = r0 + (size_t)8 * D;
#pragma unroll
  for (int nt = 0; nt < 8; nt++) {
    const int col = nt * 8 + pair * 2;
    uint32_t h0, l0, h1, l1;
    pack_hilo(o[nt][0] * i0, o[nt][1] * i0, h0, l0);
    pack_hilo(o[nt][2] * i1, o[nt][3] * i1, h1, l1);
    *(uint32_t*)(Oh + r0 + col) = h0;
    *(uint32_t*)(Ol + r0 + col) = l0;
    *(uint32_t*)(Oh + r1 + col) = h1;
    *(uint32_t*)(Ol + r1 + col) = l1;
  }
}

// ---------------------------------------------------------------------------
extern "C" void kernel_launch(void* const* d_in, const int* in_sizes, int n_in,
                              void* d_out, int out_size) {
  const float* query = (const float*)d_in[0];
  const float* key   = (const float*)d_in[1];
  const float* value = (const float*)d_in[2];
  const float* Wq    = (const float*)d_in[3];
  const float* bq    = (const float*)d_in[4];
  const float* Wk    = (const float*)d_in[5];
  const float* bk    = (const float*)d_in[6];
  const float* Wv    = (const float*)d_in[7];
  const float* bv    = (const float*)d_in[8];
  const float* Wo    = (const float*)d_in[9];
  const float* bo    = (const float*)d_in[10];
  float* out = (float*)d_out;

  __nv_bfloat16 *dQh, *dQl, *dKh, *dKl, *dVh, *dVl, *dAh, *dAl, *dWh, *dWl;
  cudaGetSymbolAddress((void**)&dQh, g_Qh);
  cudaGetSymbolAddress((void**)&dQl, g_Ql);
  cudaGetSymbolAddress((void**)&dKh, g_Kh);
  cudaGetSymbolAddress((void**)&dKl, g_Kl);
  cudaGetSymbolAddress((void**)&dVh, g_Vh);
  cudaGetSymbolAddress((void**)&dVl, g_Vl);
  cudaGetSymbolAddress((void**)&dAh, g_Ah);
  cudaGetSymbolAddress((void**)&dAl, g_Al);
  cudaGetSymbolAddress((void**)&dWh, g_Wh);
  cudaGetSymbolAddress((void**)&dWl, g_Wl);

  cudaFuncSetAttribute(attention_mma_kernel,
                       cudaFuncAttributeMaxDynamicSharedMemorySize, AT_SMEM);

  const int nAct = M * D;
  const int nW   = D * D;
  const int grAct = nAct / 4 / 256;
  const int grW   = nW / 4 / 256;
  dim3 ggrid(D / BN, M / BM);

  // Q projection -> (Qh,Ql)
  split_bf16_kernel<<<grW,   256>>>(Wq,    dWh, dWl, nW);
  split_bf16_kernel<<<grAct, 256>>>(query, dAh, dAl, nAct);
  gemm_mma_kernel<true><<<ggrid, 256>>>(dAh, dAl, dWh, dWl, bq, nullptr, dQh, dQl);
  // K projection -> (Kh,Kl)
  split_bf16_kernel<<<grW,   256>>>(Wk,  dWh, dWl, nW);
  split_bf16_kernel<<<grAct, 256>>>(key, dAh, dAl, nAct);
  gemm_mma_kernel<true><<<ggrid, 256>>>(dAh, dAl, dWh, dWl, bk, nullptr, dKh, dKl);
  // V projection -> (Vh,Vl)
  split_bf16_kernel<<<grW,   256>>>(Wv,    dWh, dWl, nW);
  split_bf16_kernel<<<grAct, 256>>>(value, dAh, dAl, nAct);
  gemm_mma_kernel<true><<<ggrid, 256>>>(dAh, dAl, dWh, dWl, bv, nullptr, dVh, dVl);

  // Attention -> (Ah,Al) directly (input of the output projection)
  attention_mma_kernel<<<dim3(L / 128, B * H), 256, AT_SMEM>>>(
      dQh, dQl, dKh, dKl, dVh, dVl, dAh, dAl);

  // Output projection -> fp32 out
  split_bf16_kernel<<<grW, 256>>>(Wo, dWh, dWl, nW);
  gemm_mma_kernel<false><<<ggrid, 256>>>(dAh, dAl, dWh, dWl, bo, out, nullptr,
                                         nullptr);
}